// round 15
// baseline (speedup 1.0000x reference)
#include <cuda_runtime.h>

// ---- problem constants ----
#define BB 64
#define NN 128
#define TT 16
#define NUM_CLS 600
#define MAX_H 15
#define MAX_O 15
#define NMAX 30
#define MM 450            // MAX_H * NMAX
#define HUMAN_IDX 49
#define SCORE_TH 0.2f
#define NMS_TH 0.5f
#define PEXP 2.8f

#define BM (BB * MM)      // 28800

// float offsets in the flattened output (tuple order, all f32)
#define OFF_BH   0                      // boxes_h  [B,M,4]
#define OFF_BO   115200                 // boxes_o  [B,M,4]
#define OFF_CLS  230400                 // obj_cls  [B,M]
#define OFF_LAB  259200                 // lab_gt   [B,M,600]
#define OFF_PRI  17539200               // prior    [B,2,M,600]
#define OFF_PV   52099200               // pv       [B,M]

// zero region = lab+pri, contiguous: 51,840,000 floats = 12,960,000 float4
#define N4       12960000
#define CHUNK4   19200                  // 128 rows * 150 float4 — rows never straddle
#define ZBLK     675                    // 675 * 19200 == N4 exactly
#define GRIDSZ   (BB + ZBLK)            // 739 blocks = one co-resident wave at 5/SM
#define PRI4     4320000                // (OFF_PRI-OFF_LAB)/4

// replay-safe ordering state (persist across graph replays by design)
__device__ unsigned long long g_epoch[GRIDSZ];
__device__ unsigned long long g_prog[ZBLK];   // holds epoch of last completed fill

// IoU(a,b) > th  without division (denominator strictly positive)
__device__ __forceinline__ bool iou_gt(float4 a, float4 b, float th) {
    float area_a = (a.z - a.x) * (a.w - a.y);
    float area_b = (b.z - b.x) * (b.w - b.y);
    float w = fmaxf(fminf(a.z, b.z) - fmaxf(a.x, b.x), 0.0f);
    float h = fmaxf(fminf(a.w, b.w) - fmaxf(a.y, b.y), 0.0f);
    float inter = w * h;
    return inter > th * (area_a + area_b - inter + 1e-7f);
}
__device__ __forceinline__ bool iou_ge(float4 a, float4 b, float th) {
    float area_a = (a.z - a.x) * (a.w - a.y);
    float area_b = (b.z - b.x) * (b.w - b.y);
    float w = fmaxf(fminf(a.z, b.z) - fmaxf(a.x, b.x), 0.0f);
    float h = fmaxf(fminf(a.w, b.w) - fmaxf(a.y, b.y), 0.0f);
    float inter = w * h;
    return inter >= th * (area_a + area_b - inter + 1e-7f);
}

// wait until the zero block owning float4-offset s4 has FULLY finished (epoch)
__device__ __forceinline__ void wait_chunk(unsigned long long ep, int s4) {
    volatile unsigned long long* pp =
        (volatile unsigned long long*)&g_prog[s4 / CHUNK4];
    while (*pp < ep) __nanosleep(512);
    __threadfence();    // acquire: order our later stores after observed zeros
}

// ============================================================
// Single kernel, 739 blocks (one co-resident wave):
//   blocks [64,739): zero one contiguous 128-row chunk seam-free,
//                    publish completion epoch at block end
//   blocks [0,64):  select image b, then overwrite its valid rows
//                    once the owning chunks are complete
// ============================================================
__global__ __launch_bounds__(256, 5)
void pairgen_one_kernel(const float* __restrict__ boxes,
                        const float* __restrict__ scores,
                        const int*   __restrict__ labels,
                        const float* __restrict__ tbh,
                        const float* __restrict__ tbo,
                        const int*   __restrict__ gt_labels,
                        const float* __restrict__ mapping,
                        float* __restrict__ out) {
    const int blk  = blockIdx.x;
    const int tid  = threadIdx.x;
    const int wid  = tid >> 5;
    const int lane = tid & 31;

    __shared__ unsigned long long s_ep;
    if (tid == 0) {                       // single-writer per-block slot
        unsigned long long e = g_epoch[blk] + 1;
        g_epoch[blk] = e;
        s_ep = e;
    }
    __syncthreads();
    const unsigned long long ep = s_ep;

    // ---------------- zero role (blocks 64..738) ----------------
    if (blk >= BB) {
        const int z = blk - BB;
        float4* p = (float4*)(out + OFF_LAB) + z * CHUNK4 + tid;
        const float4 z4 = make_float4(0.f, 0.f, 0.f, 0.f);
        // 75 independent stores per thread, no seams — max MLP
        #pragma unroll 5
        for (int u = 0; u < 75; u++) p[u * 256] = z4;
        __threadfence();          // release: all this thread's zeros visible
        __syncthreads();          // all threads' fences done
        if (tid == 0)
            *((volatile unsigned long long*)&g_prog[z]) = ep;
        return;
    }

    // ---------------- select + expand role (blocks 0..63) ----------------
    __shared__ float4 sb[NN];
    __shared__ float  ss[NN];
    __shared__ int    sl[NN];
    __shared__ uint4  predm[NN];
    __shared__ uint4  higher[NN];
    __shared__ unsigned int validw[4], ishw[4];
    __shared__ unsigned int kw[2][4];
    __shared__ int    sch[2];
    __shared__ float4 coords[NMAX];
    __shared__ int    labp[NMAX];
    __shared__ float  scp[NMAX];
    __shared__ int    s_nh, s_nt, s_cnt;
    __shared__ float4 stbh[TT], stbo[TT];
    __shared__ int    sgt[TT];
    __shared__ unsigned int mbits_h[NMAX], mbits_o[NMAX];
    __shared__ float  pw[NMAX];
    __shared__ uint4  slist[435];
    __shared__ unsigned int bmp[8][20];

    const int b = blk;

    if (tid < NN) {
        sb[tid] = ((const float4*)boxes)[b * NN + tid];
        ss[tid] = scores[b * NN + tid];
        sl[tid] = labels[b * NN + tid];
    } else if (tid < NN + TT) {
        const int t = tid - NN;
        stbh[t] = ((const float4*)tbh)[b * TT + t];
        stbo[t] = ((const float4*)tbo)[b * TT + t];
        sgt[t]  = gt_labels[b * TT + t];
    }
    if (tid == 0) { s_cnt = 0; sch[0] = 0; sch[1] = 0; }
    __syncthreads();

    if (wid == 0) {
        #pragma unroll
        for (int k = 0; k < 4; k++) {
            const int j = lane + 32 * k;
            const unsigned v = __ballot_sync(0xffffffffu, ss[j] >= SCORE_TH);
            const unsigned h = __ballot_sync(0xffffffffu, sl[j] == HUMAN_IDX);
            if (lane == 0) { validw[k] = v; ishw[k] = h; }
        }
    }

    // ---- phase 2: higher-rank + suppression-pred masks (warp per i) ----
    for (int i = wid; i < NN; i += 8) {
        const float4 bi = sb[i];
        const float  si = ss[i];
        const int    li = sl[i];
        const float  ki = (si >= SCORE_TH) ? si : -1.0f;
        unsigned hw[4], aw[4];
        #pragma unroll
        for (int k = 0; k < 4; k++) {
            const int j = lane + 32 * k;
            const float sj = ss[j];
            const float kj = (sj >= SCORE_TH) ? sj : -1.0f;
            hw[k] = __ballot_sync(0xffffffffu, (kj > ki) || (kj == ki && j < i));
            aw[k] = __ballot_sync(0xffffffffu,
                                  (sl[j] == li) && iou_gt(bi, sb[j], NMS_TH));
        }
        if (lane == 0) {
            higher[i] = make_uint4(hw[0], hw[1], hw[2], hw[3]);
            predm[i]  = make_uint4(hw[0] & aw[0], hw[1] & aw[1],
                                   hw[2] & aw[2], hw[3] & aw[3]);
        }
    }
    __syncthreads();

    // ---- phase 3: NMS fixed-point (exact greedy solution on DAG) ----
    if (tid < 4) kw[0][tid] = validw[tid];
    __syncthreads();
    int cur = 0;
    for (int round = 0; round < NN; round++) {
        if (tid == 0) sch[cur ^ 1] = 0;
        __syncthreads();
        if (tid < NN) {
            const uint4 p = predm[tid];
            const unsigned s = (p.x & kw[cur][0]) | (p.y & kw[cur][1])
                             | (p.z & kw[cur][2]) | (p.w & kw[cur][3]);
            const bool nk = ((validw[tid >> 5] >> (tid & 31)) & 1u) && (s == 0u);
            const unsigned bal = __ballot_sync(0xffffffffu, nk);
            if (lane == 0) {
                kw[cur ^ 1][wid] = bal;
                if (bal != kw[cur][wid]) sch[cur ^ 1] = 1;
            }
        }
        __syncthreads();
        cur ^= 1;
        if (!sch[cur]) break;
    }

    // ---- phase 4: direct slot scatter from rank popcounts ----
    {
        const unsigned k0 = kw[cur][0], k1 = kw[cur][1],
                       k2 = kw[cur][2], k3 = kw[cur][3];
        if (tid == 0) {
            const int nhT = __popc(k0 & ishw[0]) + __popc(k1 & ishw[1])
                          + __popc(k2 & ishw[2]) + __popc(k3 & ishw[3]);
            const int noT = __popc(k0 & ~ishw[0]) + __popc(k1 & ~ishw[1])
                          + __popc(k2 & ~ishw[2]) + __popc(k3 & ~ishw[3]);
            const int nh = nhT < MAX_H ? nhT : MAX_H;
            const int no = noT < MAX_O ? noT : MAX_O;
            s_nh = nh; s_nt = nh + no;
        }
        if (tid < NN) {
            const int w = tid >> 5, p = tid & 31;
            if ((kw[cur][w] >> p) & 1u) {
                const bool ish_i = (ishw[w] >> p) & 1u;
                const uint4 h = higher[tid];
                int slot = -1;
                if (ish_i) {
                    const int rh = __popc(h.x & k0 & ishw[0]) + __popc(h.y & k1 & ishw[1])
                                 + __popc(h.z & k2 & ishw[2]) + __popc(h.w & k3 & ishw[3]);
                    if (rh < MAX_H) slot = rh;
                } else {
                    const int ro = __popc(h.x & k0 & ~ishw[0]) + __popc(h.y & k1 & ~ishw[1])
                                 + __popc(h.z & k2 & ~ishw[2]) + __popc(h.w & k3 & ~ishw[3]);
                    if (ro < MAX_O) {
                        const int nhT = __popc(k0 & ishw[0]) + __popc(k1 & ishw[1])
                                      + __popc(k2 & ishw[2]) + __popc(k3 & ishw[3]);
                        slot = (nhT < MAX_H ? nhT : MAX_H) + ro;
                    }
                }
                if (slot >= 0) {
                    coords[slot] = sb[tid];
                    labp[slot]   = sl[tid];
                    scp[slot]    = ss[tid];
                }
            }
        }
    }
    __syncthreads();

    const int nh = s_nh;
    const int nt = s_nt;

    // ---- phase 6: per-slot GT-match bitmasks and s^p ----
    if (tid < NMAX) {
        unsigned bh = 0, bo = 0;
        float pwv = 0.0f;
        if (tid < nt) {
            const float4 c = coords[tid];
            #pragma unroll
            for (int t = 0; t < TT; t++) {
                if (iou_ge(c, stbh[t], 0.5f)) bh |= (1u << t);
                if (iou_ge(c, stbo[t], 0.5f)) bo |= (1u << t);
            }
            pwv = __powf(scp[tid], PEXP);
        }
        mbits_h[tid] = bh;
        mbits_o[tid] = bo;
        pw[tid] = pwv;
    }
    __syncthreads();

    // ---- phase 7: small outputs + compact valid-pair list (smem) ----
    for (int m = tid; m < MM; m += 256) {
        const int x = m / NMAX;
        const int y = m - x * NMAX;
        const bool pv = (x < nh) && (y < nt) && (x != y);
        float4 bh = make_float4(0.f, 0.f, 0.f, 0.f);
        float4 bo = bh;
        int cls = 0;
        if (pv) {
            bh = coords[x];
            bo = coords[y];
            cls = labp[y];
            const unsigned mask = mbits_h[x] & mbits_o[y];
            const int slot = atomicAdd(&s_cnt, 1);
            slist[slot] = make_uint4((unsigned)m | (mask << 16),
                                     (unsigned)cls,
                                     __float_as_uint(pw[x]),
                                     __float_as_uint(pw[y]));
        }
        const int row = b * MM + m;
        ((float4*)(out + OFF_BH))[row] = bh;
        ((float4*)(out + OFF_BO))[row] = bo;
        (out + OFF_CLS)[row] = pv ? (float)cls : 0.0f;
        (out + OFF_PV)[row]  = pv ? 1.0f : 0.0f;
    }
    __syncthreads();

    // ---- phase 8: expand valid rows after the owning chunks complete ----
    const int cnt = s_cnt;
    float4* base4 = (float4*)(out + OFF_LAB);
    for (int k = wid; k < cnt; k += 8) {
        const uint4 e = slist[k];
        const int m = (int)(e.x & 0xffffu);
        const unsigned mask = e.x >> 16;
        const int cls = (int)e.y;
        const float sh = __uint_as_float(e.z);
        const float so = __uint_as_float(e.w);

        const int labs = (b * MM + m) * 150;
        const int p0s  = PRI4 + (b * 2 * MM + m) * 150;
        const int p1s  = p0s + MM * 150;

        if (lane < 19) bmp[wid][lane] = 0;
        __syncwarp();
        if (lane < TT && ((mask >> lane) & 1u)) {
            const int c = sgt[lane];
            atomicOr(&bmp[wid][c >> 5], 1u << (c & 31));
        }
        __syncwarp();

        // ordering: our stores must land after the owners' zeros
        wait_chunk(ep, labs);
        wait_chunk(ep, p0s);
        wait_chunk(ep, p1s);
        __syncwarp();

        float4* lab = base4 + labs;
        float4* pr0 = base4 + p0s;
        float4* pr1 = base4 + p1s;
        const float4* mr = (const float4*)(mapping + cls * NUM_CLS);
        for (int i = lane; i < 150; i += 32) {
            const float4 mv = mr[i];
            pr0[i] = make_float4(mv.x * sh, mv.y * sh, mv.z * sh, mv.w * sh);
            pr1[i] = make_float4(mv.x * so, mv.y * so, mv.z * so, mv.w * so);
            const int c = i * 4;
            float4 lv;
            lv.x = ((bmp[wid][(c + 0) >> 5] >> ((c + 0) & 31)) & 1u) ? 1.0f : 0.0f;
            lv.y = ((bmp[wid][(c + 1) >> 5] >> ((c + 1) & 31)) & 1u) ? 1.0f : 0.0f;
            lv.z = ((bmp[wid][(c + 2) >> 5] >> ((c + 2) & 31)) & 1u) ? 1.0f : 0.0f;
            lv.w = ((bmp[wid][(c + 3) >> 5] >> ((c + 3) & 31)) & 1u) ? 1.0f : 0.0f;
            lab[i] = lv;
        }
        __syncwarp();
    }
}

extern "C" void kernel_launch(void* const* d_in, const int* in_sizes, int n_in,
                              void* d_out, int out_size) {
    const float* boxes     = (const float*)d_in[0];
    const float* scores    = (const float*)d_in[1];
    const int*   labels    = (const int*)  d_in[2];
    const float* t_boxes_h = (const float*)d_in[3];
    const float* t_boxes_o = (const float*)d_in[4];
    const int*   gt_labels = (const int*)  d_in[5];
    const float* mapping   = (const float*)d_in[6];
    float* out = (float*)d_out;

    pairgen_one_kernel<<<GRIDSZ, 256>>>(boxes, scores, labels,
                                        t_boxes_h, t_boxes_o,
                                        gt_labels, mapping, out);
}

// round 17
// speedup vs baseline: 1.0653x; 1.0653x over previous
#include <cuda_runtime.h>

// ---- problem constants ----
#define BB 64
#define NN 128
#define TT 16
#define NUM_CLS 600
#define MAX_H 15
#define MAX_O 15
#define NMAX 30
#define MM 450            // MAX_H * NMAX
#define HUMAN_IDX 49
#define SCORE_TH 0.2f
#define NMS_TH 0.5f
#define PEXP 2.8f

#define BM (BB * MM)      // 28800

// float offsets in the flattened output (tuple order, all f32)
#define OFF_BH   0                      // boxes_h  [B,M,4]
#define OFF_BO   115200                 // boxes_o  [B,M,4]
#define OFF_CLS  230400                 // obj_cls  [B,M]
#define OFF_LAB  259200                 // lab_gt   [B,M,600]
#define OFF_PRI  17539200               // prior    [B,2,M,600]
#define OFF_PV   52099200               // pv       [B,M]

// zero region = lab+pri, contiguous: 51,840,000 floats = 12,960,000 float4
#define N4       12960000
#define ZBLK     675
#define ZSTRIDE  (ZBLK * 256)           // 172800 float4; 75 iters exactly
#define GRIDSZ   (BB + ZBLK)            // 739 blocks = one co-resident wave at 5/SM
#define PRI4     4320000                // (OFF_PRI-OFF_LAB)/4

// replay-safe sync state (monotonic across graph replays)
__device__ unsigned long long g_epoch[GRIDSZ];
__device__ unsigned long long g_done;

// select -> expansion handoff
__device__ uint4 g_list[BB][440];       // {m | mask<<16, cls, sh, so}
__device__ int   g_cnt[BB];

// IoU(a,b) > th  without division (denominator strictly positive)
__device__ __forceinline__ bool iou_gt(float4 a, float4 b, float th) {
    float area_a = (a.z - a.x) * (a.w - a.y);
    float area_b = (b.z - b.x) * (b.w - b.y);
    float w = fmaxf(fminf(a.z, b.z) - fmaxf(a.x, b.x), 0.0f);
    float h = fmaxf(fminf(a.w, b.w) - fmaxf(a.y, b.y), 0.0f);
    float inter = w * h;
    return inter > th * (area_a + area_b - inter + 1e-7f);
}
__device__ __forceinline__ bool iou_ge(float4 a, float4 b, float th) {
    float area_a = (a.z - a.x) * (a.w - a.y);
    float area_b = (b.z - b.x) * (b.w - b.y);
    float w = fmaxf(fminf(a.z, b.z) - fmaxf(a.x, b.x), 0.0f);
    float h = fmaxf(fminf(a.w, b.w) - fmaxf(a.y, b.y), 0.0f);
    float inter = w * h;
    return inter >= th * (area_a + area_b - inter + 1e-7f);
}

// ============================================================
// Single kernel, 739 blocks, one co-resident wave:
//   blocks [64,739): interleaved flat zero of lab+pri (max BW)
//   blocks [0,64):  per-image selection, publish compact lists
//   global barrier (epoch-based, replay-safe)
//   ALL blocks: expansion, ~1 valid row per warp
// ============================================================
__global__ __launch_bounds__(256, 5)
void pairgen_one_kernel(const float* __restrict__ boxes,
                        const float* __restrict__ scores,
                        const int*   __restrict__ labels,
                        const float* __restrict__ tbh,
                        const float* __restrict__ tbo,
                        const int*   __restrict__ gt_labels,
                        const float* __restrict__ mapping,
                        float* __restrict__ out) {
    const int blk  = blockIdx.x;
    const int tid  = threadIdx.x;
    const int wid  = tid >> 5;
    const int lane = tid & 31;

    __shared__ unsigned long long s_ep;
    __shared__ unsigned int bmp[8][20];
    // select-role shared state (unused by zero blocks)
    __shared__ float4 sb[NN];
    __shared__ float  ss[NN];
    __shared__ int    sl[NN];
    __shared__ uint4  predm[NN];
    __shared__ uint4  higher[NN];
    __shared__ unsigned int validw[4], ishw[4];
    __shared__ unsigned int kw[2][4];
    __shared__ int    sch[2];
    __shared__ float4 coords[NMAX];
    __shared__ int    labp[NMAX];
    __shared__ float  scp[NMAX];
    __shared__ int    s_nh, s_nt, s_cnt;
    __shared__ float4 stbh[TT], stbo[TT];
    __shared__ unsigned int mbits_h[NMAX], mbits_o[NMAX];
    __shared__ float  pw[NMAX];

    if (tid == 0) {                       // single-writer per-block epoch slot
        unsigned long long e = g_epoch[blk] + 1;
        g_epoch[blk] = e;
        s_ep = e;
    }
    __syncthreads();
    const unsigned long long ep = s_ep;

    if (blk >= BB) {
        // ---------------- zero role: interleaved flat stream ----------------
        float4* p = (float4*)(out + OFF_LAB) + (blk - BB) * 256 + tid;
        const float4 z4 = make_float4(0.f, 0.f, 0.f, 0.f);
        #pragma unroll 5
        for (int u = 0; u < 75; u++) p[(size_t)u * ZSTRIDE] = z4;
    } else {
        // ---------------- select role (blocks 0..63) ----------------
        const int b = blk;

        if (tid < NN) {
            sb[tid] = ((const float4*)boxes)[b * NN + tid];
            ss[tid] = scores[b * NN + tid];
            sl[tid] = labels[b * NN + tid];
        } else if (tid < NN + TT) {
            const int t = tid - NN;
            stbh[t] = ((const float4*)tbh)[b * TT + t];
            stbo[t] = ((const float4*)tbo)[b * TT + t];
        }
        if (tid == 0) { s_cnt = 0; sch[0] = 0; sch[1] = 0; }
        __syncthreads();

        if (wid == 0) {
            #pragma unroll
            for (int k = 0; k < 4; k++) {
                const int j = lane + 32 * k;
                const unsigned v = __ballot_sync(0xffffffffu, ss[j] >= SCORE_TH);
                const unsigned h = __ballot_sync(0xffffffffu, sl[j] == HUMAN_IDX);
                if (lane == 0) { validw[k] = v; ishw[k] = h; }
            }
        }

        // ---- rank + suppression-pred masks (warp per i) ----
        for (int i = wid; i < NN; i += 8) {
            const float4 bi = sb[i];
            const float  si = ss[i];
            const int    li = sl[i];
            const float  ki = (si >= SCORE_TH) ? si : -1.0f;
            unsigned hw[4], aw[4];
            #pragma unroll
            for (int k = 0; k < 4; k++) {
                const int j = lane + 32 * k;
                const float sj = ss[j];
                const float kj = (sj >= SCORE_TH) ? sj : -1.0f;
                hw[k] = __ballot_sync(0xffffffffu, (kj > ki) || (kj == ki && j < i));
                aw[k] = __ballot_sync(0xffffffffu,
                                      (sl[j] == li) && iou_gt(bi, sb[j], NMS_TH));
            }
            if (lane == 0) {
                higher[i] = make_uint4(hw[0], hw[1], hw[2], hw[3]);
                predm[i]  = make_uint4(hw[0] & aw[0], hw[1] & aw[1],
                                       hw[2] & aw[2], hw[3] & aw[3]);
            }
        }
        __syncthreads();

        // ---- NMS fixed-point (exact greedy solution on DAG) ----
        if (tid < 4) kw[0][tid] = validw[tid];
        __syncthreads();
        int cur = 0;
        for (int round = 0; round < NN; round++) {
            if (tid == 0) sch[cur ^ 1] = 0;
            __syncthreads();
            if (tid < NN) {
                const uint4 p = predm[tid];
                const unsigned s = (p.x & kw[cur][0]) | (p.y & kw[cur][1])
                                 | (p.z & kw[cur][2]) | (p.w & kw[cur][3]);
                const bool nk = ((validw[tid >> 5] >> (tid & 31)) & 1u) && (s == 0u);
                const unsigned bal = __ballot_sync(0xffffffffu, nk);
                if (lane == 0) {
                    kw[cur ^ 1][wid] = bal;
                    if (bal != kw[cur][wid]) sch[cur ^ 1] = 1;
                }
            }
            __syncthreads();
            cur ^= 1;
            if (!sch[cur]) break;
        }

        // ---- direct slot scatter from rank popcounts ----
        {
            const unsigned k0 = kw[cur][0], k1 = kw[cur][1],
                           k2 = kw[cur][2], k3 = kw[cur][3];
            if (tid == 0) {
                const int nhT = __popc(k0 & ishw[0]) + __popc(k1 & ishw[1])
                              + __popc(k2 & ishw[2]) + __popc(k3 & ishw[3]);
                const int noT = __popc(k0 & ~ishw[0]) + __popc(k1 & ~ishw[1])
                              + __popc(k2 & ~ishw[2]) + __popc(k3 & ~ishw[3]);
                const int nh = nhT < MAX_H ? nhT : MAX_H;
                const int no = noT < MAX_O ? noT : MAX_O;
                s_nh = nh; s_nt = nh + no;
            }
            if (tid < NN) {
                const int w = tid >> 5, p = tid & 31;
                if ((kw[cur][w] >> p) & 1u) {
                    const bool ish_i = (ishw[w] >> p) & 1u;
                    const uint4 h = higher[tid];
                    int slot = -1;
                    if (ish_i) {
                        const int rh = __popc(h.x & k0 & ishw[0]) + __popc(h.y & k1 & ishw[1])
                                     + __popc(h.z & k2 & ishw[2]) + __popc(h.w & k3 & ishw[3]);
                        if (rh < MAX_H) slot = rh;
                    } else {
                        const int ro = __popc(h.x & k0 & ~ishw[0]) + __popc(h.y & k1 & ~ishw[1])
                                     + __popc(h.z & k2 & ~ishw[2]) + __popc(h.w & k3 & ~ishw[3]);
                        if (ro < MAX_O) {
                            const int nhT = __popc(k0 & ishw[0]) + __popc(k1 & ishw[1])
                                          + __popc(k2 & ishw[2]) + __popc(k3 & ishw[3]);
                            slot = (nhT < MAX_H ? nhT : MAX_H) + ro;
                        }
                    }
                    if (slot >= 0) {
                        coords[slot] = sb[tid];
                        labp[slot]   = sl[tid];
                        scp[slot]    = ss[tid];
                    }
                }
            }
        }
        __syncthreads();

        const int nh = s_nh;
        const int nt = s_nt;

        // ---- per-slot GT-match bitmasks and s^p ----
        if (tid < NMAX) {
            unsigned bh = 0, bo = 0;
            float pwv = 0.0f;
            if (tid < nt) {
                const float4 c = coords[tid];
                #pragma unroll
                for (int t = 0; t < TT; t++) {
                    if (iou_ge(c, stbh[t], 0.5f)) bh |= (1u << t);
                    if (iou_ge(c, stbo[t], 0.5f)) bo |= (1u << t);
                }
                pwv = __powf(scp[tid], PEXP);
            }
            mbits_h[tid] = bh;
            mbits_o[tid] = bo;
            pw[tid] = pwv;
        }
        __syncthreads();

        // ---- small outputs + publish compact valid-pair list ----
        for (int m = tid; m < MM; m += 256) {
            const int x = m / NMAX;
            const int y = m - x * NMAX;
            const bool pv = (x < nh) && (y < nt) && (x != y);
            float4 bh = make_float4(0.f, 0.f, 0.f, 0.f);
            float4 bo = bh;
            int cls = 0;
            if (pv) {
                bh = coords[x];
                bo = coords[y];
                cls = labp[y];
                const unsigned mask = mbits_h[x] & mbits_o[y];
                const int slot = atomicAdd(&s_cnt, 1);
                g_list[b][slot] = make_uint4((unsigned)m | (mask << 16),
                                             (unsigned)cls,
                                             __float_as_uint(pw[x]),
                                             __float_as_uint(pw[y]));
            }
            const int row = b * MM + m;
            ((float4*)(out + OFF_BH))[row] = bh;
            ((float4*)(out + OFF_BO))[row] = bo;
            (out + OFF_CLS)[row] = pv ? (float)cls : 0.0f;
            (out + OFF_PV)[row]  = pv ? 1.0f : 0.0f;
        }
        __syncthreads();
        if (tid == 0) g_cnt[b] = s_cnt;
    }

    // ================= global barrier (replay-safe, one wave) =================
    __threadfence();                      // release this block's writes
    __syncthreads();
    if (tid == 0) {
        atomicAdd(&g_done, 1ULL);
        volatile unsigned long long* pd = (volatile unsigned long long*)&g_done;
        const unsigned long long need = ep * (unsigned long long)GRIDSZ;
        while (*pd < need) __nanosleep(256);
    }
    __syncthreads();
    __threadfence();                      // acquire

    // ================= expansion: all 739 blocks, ~1 row per warp =============
    {
        const int gw  = blk * 8 + wid;    // 0..5911
        const int img = gw & 63;
        const int cnt = g_cnt[img];
        const int k0  = gw >> 6;          // 0..92
        if (k0 < cnt) {
            const int c_l = (lane < TT) ? gt_labels[img * TT + lane] : 0;
            float4* base4 = (float4*)(out + OFF_LAB);
            for (int k = k0; k < cnt; k += 92) {
                const uint4 e = g_list[img][k];
                const int m = (int)(e.x & 0xffffu);
                const unsigned mask = e.x >> 16;
                const int cls = (int)e.y;
                const float sh = __uint_as_float(e.z);
                const float so = __uint_as_float(e.w);

                const float4* mr = (const float4*)(mapping + cls * NUM_CLS);
                // batch the 5 row loads (independent; one latency)
                float4 mv0 = mr[lane];
                float4 mv1 = mr[lane + 32];
                float4 mv2 = mr[lane + 64];
                float4 mv3 = mr[lane + 96];
                float4 mv4 = make_float4(0.f, 0.f, 0.f, 0.f);
                if (lane < 22) mv4 = mr[lane + 128];

                if (lane < 19) bmp[wid][lane] = 0;
                __syncwarp();
                if (lane < TT && ((mask >> lane) & 1u))
                    atomicOr(&bmp[wid][c_l >> 5], 1u << (c_l & 31));
                __syncwarp();

                float4* lab = base4 + (img * MM + m) * 150;
                float4* pr0 = base4 + PRI4 + (img * 2 * MM + m) * 150;
                float4* pr1 = pr0 + MM * 150;

                #define EMIT(S, MV) do {                                          \
                    const int i_ = lane + 32 * (S);                               \
                    pr0[i_] = make_float4((MV).x * sh, (MV).y * sh,               \
                                          (MV).z * sh, (MV).w * sh);              \
                    pr1[i_] = make_float4((MV).x * so, (MV).y * so,               \
                                          (MV).z * so, (MV).w * so);              \
                    const int c_ = i_ * 4;                                        \
                    float4 lv_;                                                   \
                    lv_.x = ((bmp[wid][(c_+0)>>5] >> ((c_+0)&31)) & 1u) ? 1.f:0.f;\
                    lv_.y = ((bmp[wid][(c_+1)>>5] >> ((c_+1)&31)) & 1u) ? 1.f:0.f;\
                    lv_.z = ((bmp[wid][(c_+2)>>5] >> ((c_+2)&31)) & 1u) ? 1.f:0.f;\
                    lv_.w = ((bmp[wid][(c_+3)>>5] >> ((c_+3)&31)) & 1u) ? 1.f:0.f;\
                    lab[i_] = lv_;                                                \
                } while (0)

                EMIT(0, mv0); EMIT(1, mv1); EMIT(2, mv2); EMIT(3, mv3);
                if (lane < 22) EMIT(4, mv4);
                #undef EMIT
                __syncwarp();
            }
        }
    }
}

extern "C" void kernel_launch(void* const* d_in, const int* in_sizes, int n_in,
                              void* d_out, int out_size) {
    const float* boxes     = (const float*)d_in[0];
    const float* scores    = (const float*)d_in[1];
    const int*   labels    = (const int*)  d_in[2];
    const float* t_boxes_h = (const float*)d_in[3];
    const float* t_boxes_o = (const float*)d_in[4];
    const int*   gt_labels = (const int*)  d_in[5];
    const float* mapping   = (const float*)d_in[6];
    float* out = (float*)d_out;

    pairgen_one_kernel<<<GRIDSZ, 256>>>(boxes, scores, labels,
                                        t_boxes_h, t_boxes_o,
                                        gt_labels, mapping, out);
}